// round 9
// baseline (speedup 1.0000x reference)
#include <cuda_runtime.h>
#include <cuda_bf16.h>
#include <cuda_fp16.h>
#include <math.h>
#include <stdint.h>

#define NIP       256
#define N_INNER   16
#define NET_DIM   64
#define N_INPUT   784
#define N_CAT     256
#define TWO_PI    6.283185307179586f

#define PADC  260   // logits row pitch (words)
#define FFQ_P 260   // ff paired-row pitch in uint2 (banks 8T+2gq+{0,1})
#define HP    72    // his row pitch in halfs (144B: ldmatrix conflict-free)

// smem word offsets (input path); inner path reuses the low region
#define OFF_BUF0 0                       // 8320 words: ff tile / logits tile 0
#define OFF_HIS  (16 * FFQ_P * 2)        // 8320: his, 256*36 = 9216 words
#define OFF_BUF1 (OFF_HIS + 256 * (HP/2))// 17536: logits tile 1, 8320 words
#define OFF_IC   (OFF_BUF1 + 32 * PADC)  // 25856: coeff, 32 words
#define SMEM_WORDS (OFF_IC + 32)

// ---------------------------------------------------------------------------
// helpers
// ---------------------------------------------------------------------------
__device__ __forceinline__ float tanha(float x) {
    float y;
    asm("tanh.approx.f32 %0, %1;" : "=f"(y) : "f"(x));
    return y;
}

__device__ __forceinline__ float softplus_f(float x) {
    float ax = fabsf(x);
    return fmaxf(x, 0.0f) + log1pf(__expf(-ax));
}

__device__ __forceinline__ float warp_sum(float v) {
    #pragma unroll
    for (int o = 16; o > 0; o >>= 1)
        v += __shfl_xor_sync(0xffffffffu, v, o);
    return v;
}

__device__ __forceinline__ uint32_t packh(float a, float b) {
    __half2 h = __floats2half2_rn(a, b);
    return *(uint32_t*)&h;
}

// fp16 word w (packing halfs 2w,2w+1) -> ff paired layout (uint2 idx, sel)
__device__ __forceinline__ int ffq_word_addr(int w, int col) {
    const int idx = 4 * (w >> 3) + (w & 3);
    const int sel = (w >> 2) & 1;
    return (idx * FFQ_P + col) * 2 + sel;
}

// D += A(16x16,row) * B(16x8,col), fp16 inputs, fp32 accum
__device__ __forceinline__ void mma_f16(float* c, const uint32_t* a,
                                        uint32_t b0, uint32_t b1) {
    asm volatile(
        "mma.sync.aligned.m16n8k16.row.col.f32.f16.f16.f32 "
        "{%0,%1,%2,%3}, {%4,%5,%6,%7}, {%8,%9}, {%0,%1,%2,%3};"
        : "+f"(c[0]), "+f"(c[1]), "+f"(c[2]), "+f"(c[3])
        : "r"(a[0]), "r"(a[1]), "r"(a[2]), "r"(a[3]), "r"(b0), "r"(b1));
}

__device__ __forceinline__ void ldsm_x4(uint32_t* r, const __half* p) {
    uint32_t addr = (uint32_t)__cvta_generic_to_shared(p);
    asm volatile(
        "ldmatrix.sync.aligned.m8n8.x4.shared.b16 {%0,%1,%2,%3}, [%4];"
        : "=r"(r[0]), "=r"(r[1]), "=r"(r[2]), "=r"(r[3]) : "r"(addr));
}

extern __shared__ float s_dyn[];

// ---------------------------------------------------------------------------
// Inner-net path. Block = i, 512 threads, warp = g. fp16 mma, LDS.64 B pairs.
// ---------------------------------------------------------------------------
__device__ void inner_path(
    int i,
    const float* __restrict__ z, const float* __restrict__ log_w,
    const float* __restrict__ coeff,   // [2][32]
    const float* __restrict__ w1,      // [1024][64]
    const float* __restrict__ w2,      // [16][64]
    float* __restrict__ out)           // [16][256][256]
{
    uint2*    ffQ      = (uint2*)s_dyn;               // 16 * FFQ_P uint2
    uint32_t* ffW      = (uint32_t*)s_dyn;            // word view for writes
    float*    logits_s = s_dyn + 16 * FFQ_P * 2;      // 16 * 256
    float*    logw_s   = logits_s + 16 * 256;         // 256
    float*    cc       = logw_s + 256;                // 64

    const int tid  = threadIdx.x;
    const int lane = tid & 31;
    const int warp = tid >> 5;

    if (tid < 64) cc[tid] = coeff[tid];
    if (tid < 256) logw_s[tid] = log_w[tid];
    __syncthreads();

    // ---- fourier features: fp16 word m packs (ff[2m], ff[2m+1]) ----
    {
        const int j  = tid & 255;
        const int kh = tid >> 8;
        const float zi = z[i];
        const float zj = z[j];
        #pragma unroll
        for (int q = 0; q < 8; q++) {
            const int m = kh * 8 + q;
            float a0 = TWO_PI * fmaf(zi, cc[2 * m],     zj * cc[32 + 2 * m]);
            float a1 = TWO_PI * fmaf(zi, cc[2 * m + 1], zj * cc[32 + 2 * m + 1]);
            float s0, c0, s1, c1;
            __sincosf(a0, &s0, &c0);
            __sincosf(a1, &s1, &c1);
            ffW[ffq_word_addr(m, j)]      = packh(c0, c1);
            ffW[ffq_word_addr(16 + m, j)] = packh(s0, s1);
        }
    }
    __syncthreads();

    const int g  = warp;
    const int gq = lane >> 2;
    const int T  = lane & 3;
    const float* w1g = w1 + g * (NET_DIM * NET_DIM);
    const float* w2g = w2 + g * NET_DIM;

    for (int h = 0; h < 4; h++) {          // j quarters of 64
        float plog[16];
        #pragma unroll
        for (int e = 0; e < 16; e++) plog[e] = 0.0f;

        for (int mt = 0; mt < 4; mt++) {   // d tiles of 16
            uint32_t A[4][4];
            const float* r0p = w1g + (mt * 16 + gq) * 64;
            const float* r1p = w1g + (mt * 16 + 8 + gq) * 64;
            #pragma unroll
            for (int kk = 0; kk < 4; kk++) {
                float2 v0 = *(const float2*)(r0p + 16 * kk + 2 * T);
                float2 v1 = *(const float2*)(r1p + 16 * kk + 2 * T);
                float2 v2 = *(const float2*)(r0p + 16 * kk + 8 + 2 * T);
                float2 v3 = *(const float2*)(r1p + 16 * kk + 8 + 2 * T);
                A[kk][0] = packh(v0.x, v0.y);
                A[kk][1] = packh(v1.x, v1.y);
                A[kk][2] = packh(v2.x, v2.y);
                A[kk][3] = packh(v3.x, v3.y);
            }
            const float w2a = w2g[mt * 16 + gq];
            const float w2b = w2g[mt * 16 + 8 + gq];

            #pragma unroll
            for (int ntp = 0; ntp < 4; ntp++) {   // 2 n-tiles (16 j) per iter
                const int j0 = h * 64 + ntp * 16;
                float acc0[4] = {0.f, 0.f, 0.f, 0.f};
                float acc1[4] = {0.f, 0.f, 0.f, 0.f};
                #pragma unroll
                for (int kk = 0; kk < 4; kk++) {
                    uint2 Ba = ffQ[(4 * kk + T) * FFQ_P + j0 + gq];
                    uint2 Bb = ffQ[(4 * kk + T) * FFQ_P + j0 + 8 + gq];
                    mma_f16(acc0, A[kk], Ba.x, Ba.y);
                    mma_f16(acc1, A[kk], Bb.x, Bb.y);
                }
                plog[ntp * 4 + 0] += w2a * tanha(acc0[0]) + w2b * tanha(acc0[2]);
                plog[ntp * 4 + 1] += w2a * tanha(acc0[1]) + w2b * tanha(acc0[3]);
                plog[ntp * 4 + 2] += w2a * tanha(acc1[0]) + w2b * tanha(acc1[2]);
                plog[ntp * 4 + 3] += w2a * tanha(acc1[1]) + w2b * tanha(acc1[3]);
            }
        }

        // reduce over d-lanes (gq bits) and store v = lg + log_w
        #pragma unroll
        for (int e = 0; e < 16; e++) {
            float v = plog[e];
            v += __shfl_xor_sync(0xffffffffu, v, 4);
            v += __shfl_xor_sync(0xffffffffu, v, 8);
            v += __shfl_xor_sync(0xffffffffu, v, 16);
            if (lane < 4) {
                const int j = h * 64 + (e >> 2) * 16 + ((e >> 1) & 1) * 8
                            + 2 * T + (e & 1);
                logits_s[g * 256 + j] = -softplus_f(v) + logw_s[j];
            }
        }
    }
    __syncwarp();

    // ---- per-warp logsumexp over j (bounded: no max pass) ----
    {
        float vals[8];
        float se = 0.0f;
        #pragma unroll
        for (int q = 0; q < 8; q++) {
            vals[q] = logits_s[g * 256 + q * 32 + lane];
            se += __expf(vals[q]);
        }
        se = warp_sum(se);
        const float lse = __logf(se);

        float* og = out + (size_t)g * (NIP * NIP);
        #pragma unroll
        for (int q = 0; q < 8; q++)
            og[(size_t)(q * 32 + lane) * NIP + i] = __expf(vals[q] - lse);
    }
}

// ---------------------------------------------------------------------------
// Input-net path. Block = g, 512 threads. fp16 mma; ldmatrix stage-2 A;
// double-buffered logits; 1 barrier per pass.
// ---------------------------------------------------------------------------
__device__ void input_path(
    int g,
    const float* __restrict__ z,
    const float* __restrict__ coeff,   // [32]
    const float* __restrict__ w1,      // [784*64][64]
    const float* __restrict__ w2,      // [784][256][64]
    float* __restrict__ out)           // [784][256][256]
{
    uint2*    ffQ  = (uint2*)s_dyn;                  // 16 * FFQ_P uint2
    uint32_t* ffW  = (uint32_t*)s_dyn;
    float*    buf0 = s_dyn + OFF_BUF0;               // logits tile 0 (alias ff)
    __half*   hisH = (__half*)(s_dyn + OFF_HIS);     // [256][HP] halfs
    float*    buf1 = s_dyn + OFF_BUF1;               // logits tile 1
    float*    ic   = s_dyn + OFF_IC;                 // 32

    const int tid  = threadIdx.x;
    const int lane = tid & 31;
    const int warp = tid >> 5;
    const int gq   = lane >> 2;
    const int T    = lane & 3;

    if (tid < 32) ic[tid] = coeff[tid];
    __syncthreads();

    // ---- fourier features ----
    {
        const int n  = tid & 255;
        const int kh = tid >> 8;
        const float zn = z[n];
        #pragma unroll
        for (int q = 0; q < 8; q++) {
            const int m = kh * 8 + q;
            float s0, c0, s1, c1;
            __sincosf(TWO_PI * zn * ic[2 * m],     &s0, &c0);
            __sincosf(TWO_PI * zn * ic[2 * m + 1], &s1, &c1);
            ffW[ffq_word_addr(m, n)]      = packh(c0, c1);
            ffW[ffq_word_addr(16 + m, n)] = packh(s0, s1);
        }
    }
    __syncthreads();

    // ---- stage 1: H via fp16 mma, write fp16 his[n][d] flat (pitch HP) ----
    {
        const int mt = warp & 3;
        const int nb = warp >> 2;
        const float* w1g = w1 + (size_t)g * 4096;

        uint32_t A1[4][4];
        const float* r0p = w1g + (mt * 16 + gq) * 64;
        const float* r1p = w1g + (mt * 16 + 8 + gq) * 64;
        #pragma unroll
        for (int kk = 0; kk < 4; kk++) {
            float2 v0 = *(const float2*)(r0p + 16 * kk + 2 * T);
            float2 v1 = *(const float2*)(r1p + 16 * kk + 2 * T);
            float2 v2 = *(const float2*)(r0p + 16 * kk + 8 + 2 * T);
            float2 v3 = *(const float2*)(r1p + 16 * kk + 8 + 2 * T);
            A1[kk][0] = packh(v0.x, v0.y);
            A1[kk][1] = packh(v1.x, v1.y);
            A1[kk][2] = packh(v2.x, v2.y);
            A1[kk][3] = packh(v3.x, v3.y);
        }

        const int d0 = mt * 16 + gq;

        #pragma unroll
        for (int t = 0; t < 8; t++) {
            const int n0 = nb * 64 + t * 8;
            float acc[4] = {0.f, 0.f, 0.f, 0.f};
            #pragma unroll
            for (int kk = 0; kk < 4; kk++) {
                uint2 B = ffQ[(4 * kk + T) * FFQ_P + n0 + gq];
                mma_f16(acc, A1[kk], B.x, B.y);
            }
            const int na = n0 + 2 * T;
            hisH[na       * HP + d0]     = __float2half_rn(tanha(acc[0]));
            hisH[(na + 1) * HP + d0]     = __float2half_rn(tanha(acc[1]));
            hisH[na       * HP + d0 + 8] = __float2half_rn(tanha(acc[2]));
            hisH[(na + 1) * HP + d0 + 8] = __float2half_rn(tanha(acc[3]));
        }
    }
    __syncthreads();   // his done; ff region free -> buf0

    // ---- stage 2: logits[n][c] via fp16 mma, W2 in regs, A via ldmatrix ----
    const int cb = warp * 16;
    uint32_t Bw[2][4][2];
    {
        const float* w2g = w2 + (size_t)g * 256 * 64;
        #pragma unroll
        for (int ct = 0; ct < 2; ct++) {
            const float* w2c = w2g + (cb + ct * 8 + gq) * 64;
            #pragma unroll
            for (int kk = 0; kk < 4; kk++) {
                float2 u0 = *(const float2*)(w2c + 16 * kk + 2 * T);
                float2 u1 = *(const float2*)(w2c + 16 * kk + 8 + 2 * T);
                Bw[ct][kk][0] = packh(u0.x, u0.y);
                Bw[ct][kk][1] = packh(u1.x, u1.y);
            }
        }
    }

    // ldmatrix per-lane row/col offsets (within a 16-row m-tile)
    const int lm_row = (lane & 7) + ((lane >> 3) & 1) * 8;
    const int lm_col = ((lane >> 4) & 1) * 8;

    float* outg = out + (size_t)g * (NIP * N_CAT);

    // mma for one 32-row pass into tile buffer
    auto mma_pass = [&](int pass, float* buf) {
        const int n0 = pass * 32;
        #pragma unroll
        for (int mt2 = 0; mt2 < 2; mt2++) {
            const int m0 = n0 + mt2 * 16;
            const __half* lmbase = hisH + (m0 + lm_row) * HP + lm_col;
            uint32_t A2[4][4];
            #pragma unroll
            for (int kk = 0; kk < 4; kk++)
                ldsm_x4(A2[kk], lmbase + kk * 16);
            #pragma unroll
            for (int ct = 0; ct < 2; ct++) {
                float acc[4] = {0.f, 0.f, 0.f, 0.f};
                #pragma unroll
                for (int kk = 0; kk < 4; kk++)
                    mma_f16(acc, A2[kk], Bw[ct][kk][0], Bw[ct][kk][1]);
                const int nl = mt2 * 16 + gq;
                const int cc0 = cb + ct * 8 + 2 * T;
                *(float2*)&buf[nl       * PADC + cc0] = make_float2(acc[0], acc[1]);
                *(float2*)&buf[(nl + 8) * PADC + cc0] = make_float2(acc[2], acc[3]);
            }
        }
    };

    // log_softmax epilogue for one pass (no max: logits bounded)
    auto epilogue = [&](int pass, const float* buf) {
        const int n0  = pass * 32;
        const int nl  = tid >> 4;
        const int sub = tid & 15;
        const float* row = buf + nl * PADC;

        float4 v[4];
        float se = 0.0f;
        #pragma unroll
        for (int q = 0; q < 4; q++) {
            v[q] = *(const float4*)(row + q * 64 + sub * 4);
            se += __expf(v[q].x) + __expf(v[q].y)
                + __expf(v[q].z) + __expf(v[q].w);
        }
        #pragma unroll
        for (int o = 1; o < 16; o <<= 1)
            se += __shfl_xor_sync(0xffffffffu, se, o);

        const float lse = __logf(se);
        float* orow = outg + (size_t)(n0 + nl) * N_CAT;
        #pragma unroll
        for (int q = 0; q < 4; q++) {
            float4 o4;
            o4.x = v[q].x - lse; o4.y = v[q].y - lse;
            o4.z = v[q].z - lse; o4.w = v[q].w - lse;
            *(float4*)(orow + q * 64 + sub * 4) = o4;
        }
    };

    // double-buffered pipeline: mma(p+1) overlaps epilogue(p); 1 sync/pass
    mma_pass(0, buf0);
    __syncthreads();
    for (int p = 0; p < 8; p++) {
        float* cur = (p & 1) ? buf1 : buf0;
        float* nxt = (p & 1) ? buf0 : buf1;
        if (p < 7) mma_pass(p + 1, nxt);
        epilogue(p, cur);
        __syncthreads();
    }
}

// ---------------------------------------------------------------------------
// Fused fat kernel: blocks 0..255 -> inner net (i), 256..1039 -> input net (g)
// ---------------------------------------------------------------------------
__global__ void __launch_bounds__(512, 2) fused_kernel(
    const float* __restrict__ z, const float* __restrict__ log_w,
    const float* __restrict__ inner_coeff,
    const float* __restrict__ inner_w1,
    const float* __restrict__ inner_w2,
    const float* __restrict__ input_coeff,
    const float* __restrict__ input_w1,
    const float* __restrict__ input_w2,
    float* __restrict__ out)
{
    if (blockIdx.x < NIP) {
        inner_path(blockIdx.x, z, log_w, inner_coeff, inner_w1, inner_w2, out);
    } else {
        input_path(blockIdx.x - NIP, z, input_coeff, input_w1, input_w2,
                   out + (size_t)N_INNER * NIP * NIP);
    }
}

// ---------------------------------------------------------------------------
// launch
// ---------------------------------------------------------------------------
extern "C" void kernel_launch(void* const* d_in, const int* in_sizes, int n_in,
                              void* d_out, int out_size) {
    (void)in_sizes; (void)n_in; (void)out_size;
    const float* z           = (const float*)d_in[0];
    const float* log_w       = (const float*)d_in[1];
    const float* inner_coeff = (const float*)d_in[2];
    const float* inner_w1    = (const float*)d_in[3];
    const float* inner_w2    = (const float*)d_in[4];
    const float* input_coeff = (const float*)d_in[5];
    const float* input_w1    = (const float*)d_in[6];
    const float* input_w2    = (const float*)d_in[7];
    float* out = (float*)d_out;

    const int smem_bytes = SMEM_WORDS * (int)sizeof(float);
    cudaFuncSetAttribute(fused_kernel,
                         cudaFuncAttributeMaxDynamicSharedMemorySize, smem_bytes);

    fused_kernel<<<NIP + N_INPUT, 512, smem_bytes>>>(
        z, log_w, inner_coeff, inner_w1, inner_w2,
        input_coeff, input_w1, input_w2, out);
}

// round 10
// speedup vs baseline: 1.5216x; 1.5216x over previous
#include <cuda_runtime.h>
#include <cuda_bf16.h>
#include <cuda_fp16.h>
#include <math.h>
#include <stdint.h>

#define NIP       256
#define N_INNER   16
#define NET_DIM   64
#define N_INPUT   784
#define N_CAT     256
#define TWO_PI    6.283185307179586f

#define PADC  260   // logits row pitch (words)
#define FFQ_P 260   // ff paired-row pitch in uint2 (banks 8T+2gq+{0,1})
#define HP    72    // his row pitch in halfs (144B: ldmatrix conflict-free)

// smem layout (words). logits aliases ff region. Total 17568 w = 70.3 KB.
#define OFF_HIS  (16 * FFQ_P * 2)          // 8320
#define OFF_IC   (OFF_HIS + 256 * (HP/2))  // 8320 + 9216 = 17536
#define SMEM_WORDS (OFF_IC + 32)

// ---------------------------------------------------------------------------
// helpers
// ---------------------------------------------------------------------------
__device__ __forceinline__ float tanha(float x) {
    float y;
    asm("tanh.approx.f32 %0, %1;" : "=f"(y) : "f"(x));
    return y;
}

__device__ __forceinline__ float softplus_f(float x) {
    float ax = fabsf(x);
    return fmaxf(x, 0.0f) + log1pf(__expf(-ax));
}

__device__ __forceinline__ float warp_sum(float v) {
    #pragma unroll
    for (int o = 16; o > 0; o >>= 1)
        v += __shfl_xor_sync(0xffffffffu, v, o);
    return v;
}

__device__ __forceinline__ uint32_t packh(float a, float b) {
    __half2 h = __floats2half2_rn(a, b);
    return *(uint32_t*)&h;
}

// fp16 word w (packing halfs 2w,2w+1) -> ff paired layout (uint2 idx, sel)
__device__ __forceinline__ int ffq_word_addr(int w, int col) {
    const int idx = 4 * (w >> 3) + (w & 3);
    const int sel = (w >> 2) & 1;
    return (idx * FFQ_P + col) * 2 + sel;
}

// D += A(16x16,row) * B(16x8,col), fp16 inputs, fp32 accum
__device__ __forceinline__ void mma_f16(float* c, const uint32_t* a,
                                        uint32_t b0, uint32_t b1) {
    asm volatile(
        "mma.sync.aligned.m16n8k16.row.col.f32.f16.f16.f32 "
        "{%0,%1,%2,%3}, {%4,%5,%6,%7}, {%8,%9}, {%0,%1,%2,%3};"
        : "+f"(c[0]), "+f"(c[1]), "+f"(c[2]), "+f"(c[3])
        : "r"(a[0]), "r"(a[1]), "r"(a[2]), "r"(a[3]), "r"(b0), "r"(b1));
}

__device__ __forceinline__ void ldsm_x4(uint32_t* r, const __half* p) {
    uint32_t addr = (uint32_t)__cvta_generic_to_shared(p);
    asm volatile(
        "ldmatrix.sync.aligned.m8n8.x4.shared.b16 {%0,%1,%2,%3}, [%4];"
        : "=r"(r[0]), "=r"(r[1]), "=r"(r[2]), "=r"(r[3]) : "r"(addr));
}

extern __shared__ float s_dyn[];

// ---------------------------------------------------------------------------
// Inner-net path. Block = i, 512 threads, warp = g. fp16 mma, LDS.64 B pairs.
// ---------------------------------------------------------------------------
__device__ void inner_path(
    int i,
    const float* __restrict__ z, const float* __restrict__ log_w,
    const float* __restrict__ coeff,   // [2][32]
    const float* __restrict__ w1,      // [1024][64]
    const float* __restrict__ w2,      // [16][64]
    float* __restrict__ out)           // [16][256][256]
{
    uint2*    ffQ      = (uint2*)s_dyn;               // 16 * FFQ_P uint2
    uint32_t* ffW      = (uint32_t*)s_dyn;            // word view for writes
    float*    logits_s = s_dyn + 16 * FFQ_P * 2;      // 16 * 256
    float*    logw_s   = logits_s + 16 * 256;         // 256
    float*    cc       = logw_s + 256;                // 64

    const int tid  = threadIdx.x;
    const int lane = tid & 31;
    const int warp = tid >> 5;

    if (tid < 64) cc[tid] = coeff[tid];
    if (tid < 256) logw_s[tid] = log_w[tid];
    __syncthreads();

    // ---- fourier features: fp16 word m packs (ff[2m], ff[2m+1]) ----
    {
        const int j  = tid & 255;
        const int kh = tid >> 8;
        const float zi = z[i];
        const float zj = z[j];
        #pragma unroll
        for (int q = 0; q < 8; q++) {
            const int m = kh * 8 + q;
            float a0 = TWO_PI * fmaf(zi, cc[2 * m],     zj * cc[32 + 2 * m]);
            float a1 = TWO_PI * fmaf(zi, cc[2 * m + 1], zj * cc[32 + 2 * m + 1]);
            float s0, c0, s1, c1;
            __sincosf(a0, &s0, &c0);
            __sincosf(a1, &s1, &c1);
            ffW[ffq_word_addr(m, j)]      = packh(c0, c1);
            ffW[ffq_word_addr(16 + m, j)] = packh(s0, s1);
        }
    }
    __syncthreads();

    const int g  = warp;
    const int gq = lane >> 2;
    const int T  = lane & 3;
    const float* w1g = w1 + g * (NET_DIM * NET_DIM);
    const float* w2g = w2 + g * NET_DIM;

    for (int h = 0; h < 4; h++) {          // j quarters of 64
        float plog[16];
        #pragma unroll
        for (int e = 0; e < 16; e++) plog[e] = 0.0f;

        for (int mt = 0; mt < 4; mt++) {   // d tiles of 16
            uint32_t A[4][4];
            const float* r0p = w1g + (mt * 16 + gq) * 64;
            const float* r1p = w1g + (mt * 16 + 8 + gq) * 64;
            #pragma unroll
            for (int kk = 0; kk < 4; kk++) {
                float2 v0 = *(const float2*)(r0p + 16 * kk + 2 * T);
                float2 v1 = *(const float2*)(r1p + 16 * kk + 2 * T);
                float2 v2 = *(const float2*)(r0p + 16 * kk + 8 + 2 * T);
                float2 v3 = *(const float2*)(r1p + 16 * kk + 8 + 2 * T);
                A[kk][0] = packh(v0.x, v0.y);
                A[kk][1] = packh(v1.x, v1.y);
                A[kk][2] = packh(v2.x, v2.y);
                A[kk][3] = packh(v3.x, v3.y);
            }
            const float w2a = w2g[mt * 16 + gq];
            const float w2b = w2g[mt * 16 + 8 + gq];

            #pragma unroll
            for (int ntp = 0; ntp < 4; ntp++) {   // 2 n-tiles (16 j) per iter
                const int j0 = h * 64 + ntp * 16;
                float acc0[4] = {0.f, 0.f, 0.f, 0.f};
                float acc1[4] = {0.f, 0.f, 0.f, 0.f};
                #pragma unroll
                for (int kk = 0; kk < 4; kk++) {
                    uint2 Ba = ffQ[(4 * kk + T) * FFQ_P + j0 + gq];
                    uint2 Bb = ffQ[(4 * kk + T) * FFQ_P + j0 + 8 + gq];
                    mma_f16(acc0, A[kk], Ba.x, Ba.y);
                    mma_f16(acc1, A[kk], Bb.x, Bb.y);
                }
                plog[ntp * 4 + 0] += w2a * tanha(acc0[0]) + w2b * tanha(acc0[2]);
                plog[ntp * 4 + 1] += w2a * tanha(acc0[1]) + w2b * tanha(acc0[3]);
                plog[ntp * 4 + 2] += w2a * tanha(acc1[0]) + w2b * tanha(acc1[2]);
                plog[ntp * 4 + 3] += w2a * tanha(acc1[1]) + w2b * tanha(acc1[3]);
            }
        }

        // reduce over d-lanes (gq bits) and store v = lg + log_w
        #pragma unroll
        for (int e = 0; e < 16; e++) {
            float v = plog[e];
            v += __shfl_xor_sync(0xffffffffu, v, 4);
            v += __shfl_xor_sync(0xffffffffu, v, 8);
            v += __shfl_xor_sync(0xffffffffu, v, 16);
            if (lane < 4) {
                const int j = h * 64 + (e >> 2) * 16 + ((e >> 1) & 1) * 8
                            + 2 * T + (e & 1);
                logits_s[g * 256 + j] = -softplus_f(v) + logw_s[j];
            }
        }
    }
    __syncwarp();

    // ---- per-warp logsumexp over j (bounded: no max pass) ----
    {
        float vals[8];
        float se = 0.0f;
        #pragma unroll
        for (int q = 0; q < 8; q++) {
            vals[q] = logits_s[g * 256 + q * 32 + lane];
            se += __expf(vals[q]);
        }
        se = warp_sum(se);
        const float lse = __logf(se);

        float* og = out + (size_t)g * (NIP * NIP);
        #pragma unroll
        for (int q = 0; q < 8; q++)
            og[(size_t)(q * 32 + lane) * NIP + i] = __expf(vals[q] - lse);
    }
}

// ---------------------------------------------------------------------------
// Input-net path. Block = g, 512 threads. fp16 mma; ldmatrix stage-2 A;
// single logits buffer (aliases ff), no-max softmax.
// ---------------------------------------------------------------------------
__device__ void input_path(
    int g,
    const float* __restrict__ z,
    const float* __restrict__ coeff,   // [32]
    const float* __restrict__ w1,      // [784*64][64]
    const float* __restrict__ w2,      // [784][256][64]
    float* __restrict__ out)           // [784][256][256]
{
    uint2*    ffQ    = (uint2*)s_dyn;                // 16 * FFQ_P uint2
    uint32_t* ffW    = (uint32_t*)s_dyn;
    float*    logits = s_dyn;                        // 32*PADC, alias of ff
    __half*   hisH   = (__half*)(s_dyn + OFF_HIS);   // [256][HP] halfs
    float*    ic     = s_dyn + OFF_IC;               // 32

    const int tid  = threadIdx.x;
    const int lane = tid & 31;
    const int warp = tid >> 5;
    const int gq   = lane >> 2;
    const int T    = lane & 3;

    if (tid < 32) ic[tid] = coeff[tid];
    __syncthreads();

    // ---- fourier features ----
    {
        const int n  = tid & 255;
        const int kh = tid >> 8;
        const float zn = z[n];
        #pragma unroll
        for (int q = 0; q < 8; q++) {
            const int m = kh * 8 + q;
            float s0, c0, s1, c1;
            __sincosf(TWO_PI * zn * ic[2 * m],     &s0, &c0);
            __sincosf(TWO_PI * zn * ic[2 * m + 1], &s1, &c1);
            ffW[ffq_word_addr(m, n)]      = packh(c0, c1);
            ffW[ffq_word_addr(16 + m, n)] = packh(s0, s1);
        }
    }
    __syncthreads();

    // ---- stage 1: H via fp16 mma, write fp16 his[n][d] flat (pitch HP) ----
    {
        const int mt = warp & 3;
        const int nb = warp >> 2;
        const float* w1g = w1 + (size_t)g * 4096;

        uint32_t A1[4][4];
        const float* r0p = w1g + (mt * 16 + gq) * 64;
        const float* r1p = w1g + (mt * 16 + 8 + gq) * 64;
        #pragma unroll
        for (int kk = 0; kk < 4; kk++) {
            float2 v0 = *(const float2*)(r0p + 16 * kk + 2 * T);
            float2 v1 = *(const float2*)(r1p + 16 * kk + 2 * T);
            float2 v2 = *(const float2*)(r0p + 16 * kk + 8 + 2 * T);
            float2 v3 = *(const float2*)(r1p + 16 * kk + 8 + 2 * T);
            A1[kk][0] = packh(v0.x, v0.y);
            A1[kk][1] = packh(v1.x, v1.y);
            A1[kk][2] = packh(v2.x, v2.y);
            A1[kk][3] = packh(v3.x, v3.y);
        }

        const int d0 = mt * 16 + gq;

        #pragma unroll
        for (int t = 0; t < 8; t++) {
            const int n0 = nb * 64 + t * 8;
            float acc[4] = {0.f, 0.f, 0.f, 0.f};
            #pragma unroll
            for (int kk = 0; kk < 4; kk++) {
                uint2 B = ffQ[(4 * kk + T) * FFQ_P + n0 + gq];
                mma_f16(acc, A1[kk], B.x, B.y);
            }
            const int na = n0 + 2 * T;
            hisH[na       * HP + d0]     = __float2half_rn(tanha(acc[0]));
            hisH[(na + 1) * HP + d0]     = __float2half_rn(tanha(acc[1]));
            hisH[na       * HP + d0 + 8] = __float2half_rn(tanha(acc[2]));
            hisH[(na + 1) * HP + d0 + 8] = __float2half_rn(tanha(acc[3]));
        }
    }
    __syncthreads();   // his done; ff region free -> logits

    // ---- stage 2: logits[n][c] via fp16 mma, W2 in regs, A via ldmatrix ----
    const int cb = warp * 16;
    uint32_t Bw[2][4][2];
    {
        const float* w2g = w2 + (size_t)g * 256 * 64;
        #pragma unroll
        for (int ct = 0; ct < 2; ct++) {
            const float* w2c = w2g + (cb + ct * 8 + gq) * 64;
            #pragma unroll
            for (int kk = 0; kk < 4; kk++) {
                float2 u0 = *(const float2*)(w2c + 16 * kk + 2 * T);
                float2 u1 = *(const float2*)(w2c + 16 * kk + 8 + 2 * T);
                Bw[ct][kk][0] = packh(u0.x, u0.y);
                Bw[ct][kk][1] = packh(u1.x, u1.y);
            }
        }
    }

    // ldmatrix per-lane row/col offsets (within a 16-row m-tile)
    const int lm_row = (lane & 7) + ((lane >> 3) & 1) * 8;
    const int lm_col = ((lane >> 4) & 1) * 8;

    float* outg = out + (size_t)g * (NIP * N_CAT);

    for (int pass = 0; pass < 8; pass++) {
        const int n0 = pass * 32;

        #pragma unroll
        for (int mt2 = 0; mt2 < 2; mt2++) {
            const int m0 = n0 + mt2 * 16;
            const __half* lmbase = hisH + (m0 + lm_row) * HP + lm_col;
            uint32_t A2[4][4];
            #pragma unroll
            for (int kk = 0; kk < 4; kk++)
                ldsm_x4(A2[kk], lmbase + kk * 16);
            #pragma unroll
            for (int ct = 0; ct < 2; ct++) {
                float acc[4] = {0.f, 0.f, 0.f, 0.f};
                #pragma unroll
                for (int kk = 0; kk < 4; kk++)
                    mma_f16(acc, A2[kk], Bw[ct][kk][0], Bw[ct][kk][1]);
                const int nl = mt2 * 16 + gq;
                const int cc0 = cb + ct * 8 + 2 * T;
                *(float2*)&logits[nl       * PADC + cc0] = make_float2(acc[0], acc[1]);
                *(float2*)&logits[(nl + 8) * PADC + cc0] = make_float2(acc[2], acc[3]);
            }
        }
        __syncthreads();

        // epilogue: log_softmax over c (no max: logits bounded)
        {
            const int nl  = tid >> 4;
            const int sub = tid & 15;
            const float* row = logits + nl * PADC;

            float4 v[4];
            float se = 0.0f;
            #pragma unroll
            for (int q = 0; q < 4; q++) {
                v[q] = *(const float4*)(row + q * 64 + sub * 4);
                se += __expf(v[q].x) + __expf(v[q].y)
                    + __expf(v[q].z) + __expf(v[q].w);
            }
            #pragma unroll
            for (int o = 1; o < 16; o <<= 1)
                se += __shfl_xor_sync(0xffffffffu, se, o);

            const float lse = __logf(se);
            float* orow = outg + (size_t)(n0 + nl) * N_CAT;
            #pragma unroll
            for (int q = 0; q < 4; q++) {
                float4 o4;
                o4.x = v[q].x - lse; o4.y = v[q].y - lse;
                o4.z = v[q].z - lse; o4.w = v[q].w - lse;
                *(float4*)(orow + q * 64 + sub * 4) = o4;
            }
        }
        __syncthreads();
    }
}

// ---------------------------------------------------------------------------
// Fused fat kernel: blocks 0..255 -> inner net (i), 256..1039 -> input net (g)
// ---------------------------------------------------------------------------
__global__ void __launch_bounds__(512, 2) fused_kernel(
    const float* __restrict__ z, const float* __restrict__ log_w,
    const float* __restrict__ inner_coeff,
    const float* __restrict__ inner_w1,
    const float* __restrict__ inner_w2,
    const float* __restrict__ input_coeff,
    const float* __restrict__ input_w1,
    const float* __restrict__ input_w2,
    float* __restrict__ out)
{
    if (blockIdx.x < NIP) {
        inner_path(blockIdx.x, z, log_w, inner_coeff, inner_w1, inner_w2, out);
    } else {
        input_path(blockIdx.x - NIP, z, input_coeff, input_w1, input_w2,
                   out + (size_t)N_INNER * NIP * NIP);
    }
}

// ---------------------------------------------------------------------------
// launch
// ---------------------------------------------------------------------------
extern "C" void kernel_launch(void* const* d_in, const int* in_sizes, int n_in,
                              void* d_out, int out_size) {
    (void)in_sizes; (void)n_in; (void)out_size;
    const float* z           = (const float*)d_in[0];
    const float* log_w       = (const float*)d_in[1];
    const float* inner_coeff = (const float*)d_in[2];
    const float* inner_w1    = (const float*)d_in[3];
    const float* inner_w2    = (const float*)d_in[4];
    const float* input_coeff = (const float*)d_in[5];
    const float* input_w1    = (const float*)d_in[6];
    const float* input_w2    = (const float*)d_in[7];
    float* out = (float*)d_out;

    const int smem_bytes = SMEM_WORDS * (int)sizeof(float);
    cudaFuncSetAttribute(fused_kernel,
                         cudaFuncAttributeMaxDynamicSharedMemorySize, smem_bytes);

    fused_kernel<<<NIP + N_INPUT, 512, smem_bytes>>>(
        z, log_w, inner_coeff, inner_w1, inner_w2,
        input_coeff, input_w1, input_w2, out);
}

// round 11
// speedup vs baseline: 1.8090x; 1.1889x over previous
#include <cuda_runtime.h>
#include <cuda_bf16.h>
#include <cuda_fp16.h>
#include <math.h>
#include <stdint.h>

#define NIP       256
#define N_INNER   16
#define NET_DIM   64
#define N_INPUT   784
#define N_CAT     256
#define TWO_PI    6.283185307179586f

#define PADC  260   // logits row pitch (words)
#define FFQ_P 260   // ff paired-row pitch in uint2 (banks 8T+2gq+{0,1})
#define HP    72    // his row pitch in halfs (144B: ldmatrix conflict-free)

// smem layout (words). logits aliases ff region. Total 17568 w = 70.3 KB.
#define OFF_HIS  (16 * FFQ_P * 2)          // 8320
#define OFF_IC   (OFF_HIS + 256 * (HP/2))  // 8320 + 9216 = 17536
#define SMEM_WORDS (OFF_IC + 32)

// pre-converted fp16 W1 fragments, fragment-linear:
// index ((g*4 + mt)*4 + kk)*32 + lane -> uint4 {a0,a1,a2,a3}
__device__ uint4 g_w1i_frag[16 * 4 * 4 * 32];        // inner W1, 128 KB
__device__ uint4 g_w1n_frag[784 * 4 * 4 * 32];       // input W1, 6.4 MB

// ---------------------------------------------------------------------------
// helpers
// ---------------------------------------------------------------------------
__device__ __forceinline__ float tanha(float x) {
    float y;
    asm("tanh.approx.f32 %0, %1;" : "=f"(y) : "f"(x));
    return y;
}

__device__ __forceinline__ float softplus_f(float x) {
    float ax = fabsf(x);
    return fmaxf(x, 0.0f) + log1pf(__expf(-ax));
}

__device__ __forceinline__ float warp_sum(float v) {
    #pragma unroll
    for (int o = 16; o > 0; o >>= 1)
        v += __shfl_xor_sync(0xffffffffu, v, o);
    return v;
}

__device__ __forceinline__ uint32_t packh(float a, float b) {
    __half2 h = __floats2half2_rn(a, b);
    return *(uint32_t*)&h;
}

// fp16 word w (packing halfs 2w,2w+1) -> ff paired layout (uint2 idx, sel)
__device__ __forceinline__ int ffq_word_addr(int w, int col) {
    const int idx = 4 * (w >> 3) + (w & 3);
    const int sel = (w >> 2) & 1;
    return (idx * FFQ_P + col) * 2 + sel;
}

// D += A(16x16,row) * B(16x8,col), fp16 inputs, fp32 accum
__device__ __forceinline__ void mma_f16(float* c, const uint32_t* a,
                                        uint32_t b0, uint32_t b1) {
    asm volatile(
        "mma.sync.aligned.m16n8k16.row.col.f32.f16.f16.f32 "
        "{%0,%1,%2,%3}, {%4,%5,%6,%7}, {%8,%9}, {%0,%1,%2,%3};"
        : "+f"(c[0]), "+f"(c[1]), "+f"(c[2]), "+f"(c[3])
        : "r"(a[0]), "r"(a[1]), "r"(a[2]), "r"(a[3]), "r"(b0), "r"(b1));
}

__device__ __forceinline__ void ldsm_x4(uint32_t* r, const __half* p) {
    uint32_t addr = (uint32_t)__cvta_generic_to_shared(p);
    asm volatile(
        "ldmatrix.sync.aligned.m8n8.x4.shared.b16 {%0,%1,%2,%3}, [%4];"
        : "=r"(r[0]), "=r"(r[1]), "=r"(r[2]), "=r"(r[3]) : "r"(addr));
}

extern __shared__ float s_dyn[];

// ---------------------------------------------------------------------------
// Pre-pass: convert W1 (inner + input) to fp16 fragment-linear layout.
// One thread per uint4 fragment group: 800 groups of 512 threads.
// ---------------------------------------------------------------------------
__global__ void __launch_bounds__(512) convert_w1_kernel(
    const float* __restrict__ w1i,   // [16*64][64]
    const float* __restrict__ w1n)   // [784*64][64]
{
    const int idx  = blockIdx.x * 512 + threadIdx.x;
    const int lane = idx & 31;
    const int kk   = (idx >> 5) & 3;
    const int mt   = (idx >> 7) & 3;
    const int gg   = idx >> 9;           // 0..799

    const int gq = lane >> 2;
    const int T  = lane & 3;

    const float* base = (gg < 16) ? (w1i + (size_t)gg * 4096)
                                  : (w1n + (size_t)(gg - 16) * 4096);
    const float* r0 = base + (mt * 16 + gq) * 64 + 16 * kk + 2 * T;
    const float* r1 = base + (mt * 16 + 8 + gq) * 64 + 16 * kk + 2 * T;

    uint4 v;
    v.x = packh(r0[0], r0[1]);
    v.y = packh(r1[0], r1[1]);
    v.z = packh(r0[8], r0[9]);
    v.w = packh(r1[8], r1[9]);

    if (gg < 16) g_w1i_frag[idx] = v;
    else         g_w1n_frag[idx - 16 * 512] = v;
}

// ---------------------------------------------------------------------------
// Inner-net path. Block = i, 512 threads, warp = g. fp16 mma; A via LDG.128
// from fragment-linear fp16 W1.
// ---------------------------------------------------------------------------
__device__ void inner_path(
    int i,
    const float* __restrict__ z, const float* __restrict__ log_w,
    const float* __restrict__ coeff,   // [2][32]
    const float* __restrict__ w2,      // [16][64]
    float* __restrict__ out)           // [16][256][256]
{
    uint2*    ffQ      = (uint2*)s_dyn;               // 16 * FFQ_P uint2
    uint32_t* ffW      = (uint32_t*)s_dyn;            // word view for writes
    float*    logits_s = s_dyn + 16 * FFQ_P * 2;      // 16 * 256
    float*    logw_s   = logits_s + 16 * 256;         // 256
    float*    cc       = logw_s + 256;                // 64

    const int tid  = threadIdx.x;
    const int lane = tid & 31;
    const int warp = tid >> 5;

    if (tid < 64) cc[tid] = coeff[tid];
    if (tid < 256) logw_s[tid] = log_w[tid];
    __syncthreads();

    // ---- fourier features: fp16 word m packs (ff[2m], ff[2m+1]) ----
    {
        const int j  = tid & 255;
        const int kh = tid >> 8;
        const float zi = z[i];
        const float zj = z[j];
        #pragma unroll
        for (int q = 0; q < 8; q++) {
            const int m = kh * 8 + q;
            float a0 = TWO_PI * fmaf(zi, cc[2 * m],     zj * cc[32 + 2 * m]);
            float a1 = TWO_PI * fmaf(zi, cc[2 * m + 1], zj * cc[32 + 2 * m + 1]);
            float s0, c0, s1, c1;
            __sincosf(a0, &s0, &c0);
            __sincosf(a1, &s1, &c1);
            ffW[ffq_word_addr(m, j)]      = packh(c0, c1);
            ffW[ffq_word_addr(16 + m, j)] = packh(s0, s1);
        }
    }
    __syncthreads();

    const int g  = warp;
    const int gq = lane >> 2;
    const int T  = lane & 3;
    const float* w2g = w2 + g * NET_DIM;
    const uint4* w1f = g_w1i_frag + (size_t)(g * 4) * 4 * 32 + lane;

    for (int h = 0; h < 4; h++) {          // j quarters of 64
        float plog[16];
        #pragma unroll
        for (int e = 0; e < 16; e++) plog[e] = 0.0f;

        for (int mt = 0; mt < 4; mt++) {   // d tiles of 16
            uint32_t A[4][4];
            #pragma unroll
            for (int kk = 0; kk < 4; kk++) {
                uint4 v = w1f[(mt * 4 + kk) * 32];
                A[kk][0] = v.x; A[kk][1] = v.y;
                A[kk][2] = v.z; A[kk][3] = v.w;
            }
            const float w2a = w2g[mt * 16 + gq];
            const float w2b = w2g[mt * 16 + 8 + gq];

            #pragma unroll
            for (int ntp = 0; ntp < 4; ntp++) {   // 2 n-tiles (16 j) per iter
                const int j0 = h * 64 + ntp * 16;
                float acc0[4] = {0.f, 0.f, 0.f, 0.f};
                float acc1[4] = {0.f, 0.f, 0.f, 0.f};
                #pragma unroll
                for (int kk = 0; kk < 4; kk++) {
                    uint2 Ba = ffQ[(4 * kk + T) * FFQ_P + j0 + gq];
                    uint2 Bb = ffQ[(4 * kk + T) * FFQ_P + j0 + 8 + gq];
                    mma_f16(acc0, A[kk], Ba.x, Ba.y);
                    mma_f16(acc1, A[kk], Bb.x, Bb.y);
                }
                plog[ntp * 4 + 0] += w2a * tanha(acc0[0]) + w2b * tanha(acc0[2]);
                plog[ntp * 4 + 1] += w2a * tanha(acc0[1]) + w2b * tanha(acc0[3]);
                plog[ntp * 4 + 2] += w2a * tanha(acc1[0]) + w2b * tanha(acc1[2]);
                plog[ntp * 4 + 3] += w2a * tanha(acc1[1]) + w2b * tanha(acc1[3]);
            }
        }

        // reduce over d-lanes (gq bits) and store v = lg + log_w
        #pragma unroll
        for (int e = 0; e < 16; e++) {
            float v = plog[e];
            v += __shfl_xor_sync(0xffffffffu, v, 4);
            v += __shfl_xor_sync(0xffffffffu, v, 8);
            v += __shfl_xor_sync(0xffffffffu, v, 16);
            if (lane < 4) {
                const int j = h * 64 + (e >> 2) * 16 + ((e >> 1) & 1) * 8
                            + 2 * T + (e & 1);
                logits_s[g * 256 + j] = -softplus_f(v) + logw_s[j];
            }
        }
    }
    __syncwarp();

    // ---- per-warp logsumexp over j (bounded: no max pass) ----
    {
        float vals[8];
        float se = 0.0f;
        #pragma unroll
        for (int q = 0; q < 8; q++) {
            vals[q] = logits_s[g * 256 + q * 32 + lane];
            se += __expf(vals[q]);
        }
        se = warp_sum(se);
        const float lse = __logf(se);

        float* og = out + (size_t)g * (NIP * NIP);
        #pragma unroll
        for (int q = 0; q < 8; q++)
            og[(size_t)(q * 32 + lane) * NIP + i] = __expf(vals[q] - lse);
    }
}

// ---------------------------------------------------------------------------
// Input-net path. Block = g, 512 threads. fp16 mma; ldmatrix stage-2 A;
// stage-1 A via LDG.128 fragment-linear W1; no-max softmax.
// ---------------------------------------------------------------------------
__device__ void input_path(
    int g,
    const float* __restrict__ z,
    const float* __restrict__ coeff,   // [32]
    const float* __restrict__ w2,      // [784][256][64]
    float* __restrict__ out)           // [784][256][256]
{
    uint2*    ffQ    = (uint2*)s_dyn;                // 16 * FFQ_P uint2
    uint32_t* ffW    = (uint32_t*)s_dyn;
    float*    logits = s_dyn;                        // 32*PADC, alias of ff
    __half*   hisH   = (__half*)(s_dyn + OFF_HIS);   // [256][HP] halfs
    float*    ic     = s_dyn + OFF_IC;               // 32

    const int tid  = threadIdx.x;
    const int lane = tid & 31;
    const int warp = tid >> 5;
    const int gq   = lane >> 2;
    const int T    = lane & 3;

    if (tid < 32) ic[tid] = coeff[tid];
    __syncthreads();

    // ---- fourier features ----
    {
        const int n  = tid & 255;
        const int kh = tid >> 8;
        const float zn = z[n];
        #pragma unroll
        for (int q = 0; q < 8; q++) {
            const int m = kh * 8 + q;
            float s0, c0, s1, c1;
            __sincosf(TWO_PI * zn * ic[2 * m],     &s0, &c0);
            __sincosf(TWO_PI * zn * ic[2 * m + 1], &s1, &c1);
            ffW[ffq_word_addr(m, n)]      = packh(c0, c1);
            ffW[ffq_word_addr(16 + m, n)] = packh(s0, s1);
        }
    }
    __syncthreads();

    // ---- stage 1: H via fp16 mma, write fp16 his[n][d] flat (pitch HP) ----
    {
        const int mt = warp & 3;
        const int nb = warp >> 2;
        const uint4* w1f = g_w1n_frag + ((size_t)g * 4 + mt) * 4 * 32 + lane;

        uint32_t A1[4][4];
        #pragma unroll
        for (int kk = 0; kk < 4; kk++) {
            uint4 v = w1f[kk * 32];
            A1[kk][0] = v.x; A1[kk][1] = v.y;
            A1[kk][2] = v.z; A1[kk][3] = v.w;
        }

        const int d0 = mt * 16 + gq;

        #pragma unroll
        for (int t = 0; t < 8; t++) {
            const int n0 = nb * 64 + t * 8;
            float acc[4] = {0.f, 0.f, 0.f, 0.f};
            #pragma unroll
            for (int kk = 0; kk < 4; kk++) {
                uint2 B = ffQ[(4 * kk + T) * FFQ_P + n0 + gq];
                mma_f16(acc, A1[kk], B.x, B.y);
            }
            const int na = n0 + 2 * T;
            hisH[na       * HP + d0]     = __float2half_rn(tanha(acc[0]));
            hisH[(na + 1) * HP + d0]     = __float2half_rn(tanha(acc[1]));
            hisH[na       * HP + d0 + 8] = __float2half_rn(tanha(acc[2]));
            hisH[(na + 1) * HP + d0 + 8] = __float2half_rn(tanha(acc[3]));
        }
    }
    __syncthreads();   // his done; ff region free -> logits

    // ---- stage 2: logits[n][c] via fp16 mma, W2 in regs, A via ldmatrix ----
    const int cb = warp * 16;
    uint32_t Bw[2][4][2];
    {
        const float* w2g = w2 + (size_t)g * 256 * 64;
        #pragma unroll
        for (int ct = 0; ct < 2; ct++) {
            const float* w2c = w2g + (cb + ct * 8 + gq) * 64;
            #pragma unroll
            for (int kk = 0; kk < 4; kk++) {
                float2 u0 = *(const float2*)(w2c + 16 * kk + 2 * T);
                float2 u1 = *(const float2*)(w2c + 16 * kk + 8 + 2 * T);
                Bw[ct][kk][0] = packh(u0.x, u0.y);
                Bw[ct][kk][1] = packh(u1.x, u1.y);
            }
        }
    }

    // ldmatrix per-lane row/col offsets (within a 16-row m-tile)
    const int lm_row = (lane & 7) + ((lane >> 3) & 1) * 8;
    const int lm_col = ((lane >> 4) & 1) * 8;

    float* outg = out + (size_t)g * (NIP * N_CAT);

    for (int pass = 0; pass < 8; pass++) {
        const int n0 = pass * 32;

        #pragma unroll
        for (int mt2 = 0; mt2 < 2; mt2++) {
            const int m0 = n0 + mt2 * 16;
            const __half* lmbase = hisH + (m0 + lm_row) * HP + lm_col;
            uint32_t A2[4][4];
            #pragma unroll
            for (int kk = 0; kk < 4; kk++)
                ldsm_x4(A2[kk], lmbase + kk * 16);
            #pragma unroll
            for (int ct = 0; ct < 2; ct++) {
                float acc[4] = {0.f, 0.f, 0.f, 0.f};
                #pragma unroll
                for (int kk = 0; kk < 4; kk++)
                    mma_f16(acc, A2[kk], Bw[ct][kk][0], Bw[ct][kk][1]);
                const int nl = mt2 * 16 + gq;
                const int cc0 = cb + ct * 8 + 2 * T;
                *(float2*)&logits[nl       * PADC + cc0] = make_float2(acc[0], acc[1]);
                *(float2*)&logits[(nl + 8) * PADC + cc0] = make_float2(acc[2], acc[3]);
            }
        }
        __syncthreads();

        // epilogue: log_softmax over c (no max: logits bounded)
        {
            const int nl  = tid >> 4;
            const int sub = tid & 15;
            const float* row = logits + nl * PADC;

            float4 v[4];
            float se = 0.0f;
            #pragma unroll
            for (int q = 0; q < 4; q++) {
                v[q] = *(const float4*)(row + q * 64 + sub * 4);
                se += __expf(v[q].x) + __expf(v[q].y)
                    + __expf(v[q].z) + __expf(v[q].w);
            }
            #pragma unroll
            for (int o = 1; o < 16; o <<= 1)
                se += __shfl_xor_sync(0xffffffffu, se, o);

            const float lse = __logf(se);
            float* orow = outg + (size_t)(n0 + nl) * N_CAT;
            #pragma unroll
            for (int q = 0; q < 4; q++) {
                float4 o4;
                o4.x = v[q].x - lse; o4.y = v[q].y - lse;
                o4.z = v[q].z - lse; o4.w = v[q].w - lse;
                *(float4*)(orow + q * 64 + sub * 4) = o4;
            }
        }
        __syncthreads();
    }
}

// ---------------------------------------------------------------------------
// Fused fat kernel: blocks 0..255 -> inner net (i), 256..1039 -> input net (g)
// ---------------------------------------------------------------------------
__global__ void __launch_bounds__(512, 2) fused_kernel(
    const float* __restrict__ z, const float* __restrict__ log_w,
    const float* __restrict__ inner_coeff,
    const float* __restrict__ inner_w2,
    const float* __restrict__ input_coeff,
    const float* __restrict__ input_w2,
    float* __restrict__ out)
{
    if (blockIdx.x < NIP) {
        inner_path(blockIdx.x, z, log_w, inner_coeff, inner_w2, out);
    } else {
        input_path(blockIdx.x - NIP, z, input_coeff, input_w2,
                   out + (size_t)N_INNER * NIP * NIP);
    }
}

// ---------------------------------------------------------------------------
// launch
// ---------------------------------------------------------------------------
extern "C" void kernel_launch(void* const* d_in, const int* in_sizes, int n_in,
                              void* d_out, int out_size) {
    (void)in_sizes; (void)n_in; (void)out_size;
    const float* z           = (const float*)d_in[0];
    const float* log_w       = (const float*)d_in[1];
    const float* inner_coeff = (const float*)d_in[2];
    const float* inner_w1    = (const float*)d_in[3];
    const float* inner_w2    = (const float*)d_in[4];
    const float* input_coeff = (const float*)d_in[5];
    const float* input_w1    = (const float*)d_in[6];
    const float* input_w2    = (const float*)d_in[7];
    float* out = (float*)d_out;

    const int smem_bytes = SMEM_WORDS * (int)sizeof(float);
    cudaFuncSetAttribute(fused_kernel,
                         cudaFuncAttributeMaxDynamicSharedMemorySize, smem_bytes);

    // pre-pass: fp16 fragment-linear W1 (inner: 16 groups, input: 784 groups)
    convert_w1_kernel<<<800, 512>>>(inner_w1, input_w1);

    fused_kernel<<<NIP + N_INPUT, 512, smem_bytes>>>(
        z, log_w, inner_coeff, inner_w2,
        input_coeff, input_w2, out);
}